// round 1
// baseline (speedup 1.0000x reference)
#include <cuda_runtime.h>

#define WIN       1024
#define NH        64
#define SEGS      4
#define SEGLEN    (WIN / SEGS)      // 256
#define THREADS   (NH * SEGS)       // 256

// amp-normalized Morlet harmonic transform.
// One block per (b,t,c) frame. Thread (k, seg) accumulates the complex dot
// product of xw[] against exp(-i*2*pi*fc_k*n) over its 256-sample segment
// using a constant-rotation recurrence (no sincos in the inner loop).
__global__ __launch_bounds__(THREADS)
void morlet_kernel(const float* __restrict__ audio,
                   const float* __restrict__ f0,
                   float* __restrict__ out_hd,
                   float* __restrict__ out_amp)
{
    __shared__ float xw[WIN];
    __shared__ float pre[THREADS];
    __shared__ float pim[THREADS];
    __shared__ float tk[NH];
    __shared__ float red[2];

    const int frame = blockIdx.x;
    const int tid   = threadIdx.x;

    // normalizer = 1/sqrt(pi * 16000)
    const float normalizer = 0.00446031f;

    // Stage windowed samples: xw[n] = normalizer * exp(-(n-512)^2/16000) * x[n]
    const float* x = audio + (size_t)frame * WIN;
    #pragma unroll
    for (int n = tid; n < WIN; n += THREADS) {
        float d = (float)(n - WIN / 2);
        float g = __expf(-d * d * (1.0f / 16000.0f)) * normalizer;
        xw[n] = g * x[n];
    }
    __syncthreads();

    const int k   = tid & (NH - 1);      // harmonic index 0..63 (harmonic k+1)
    const int seg = tid >> 6;            // segment 0..3

    const float kf = (float)(k + 1);
    const float f  = f0[frame];
    const float fc = (f * kf) * (1.0f / 16000.0f);   // normalized frequency

    // Constant per-sample rotation r = exp(-i*2*pi*fc)
    float sr, cr;
    sincospif(-2.0f * fc, &sr, &cr);

    // Exact phasor at segment start: z = exp(-i*2*pi*fc*n0)
    const float n0  = (float)(seg * SEGLEN);
    float ph0 = fc * n0;
    float fr  = ph0 - floorf(ph0);
    float zs, zc;
    sincospif(-2.0f * fr, &zs, &zc);

    float are = 0.0f, aim = 0.0f;
    const float* xws = xw + seg * SEGLEN;

    #pragma unroll 16
    for (int n = 0; n < SEGLEN; n++) {
        float w = xws[n];                 // broadcast across the warp (same n)
        are = fmaf(zc, w, are);
        aim = fmaf(zs, w, aim);
        // z *= r  (complex multiply, 4 FMA)
        float nzc = fmaf(zc, cr, -(zs * sr));
        float nzs = fmaf(zs, cr,  (zc * sr));
        zc = nzc;
        zs = nzs;
    }

    pre[tid] = are;
    pim[tid] = aim;
    __syncthreads();

    // Combine the 4 segment partials (complex sum BEFORE abs), take magnitude.
    if (tid < NH) {
        float re = pre[tid] + pre[tid + 64] + pre[tid + 128] + pre[tid + 192];
        float im = pim[tid] + pim[tid + 64] + pim[tid + 128] + pim[tid + 192];
        float t  = sqrtf(fmaf(re, re, im * im));
        // Nyquist mask (fc of this tid is the seg==0,k==tid value)
        if (fc > 0.5f) t = 0.0f;
        tk[tid] = t;
    }
    __syncthreads();

    // Sum over harmonics -> amp_raw
    if (tid < NH) {
        float v = tk[tid];
        #pragma unroll
        for (int o = 16; o > 0; o >>= 1)
            v += __shfl_down_sync(0xffffffffu, v, o);
        if ((tid & 31) == 0) red[tid >> 5] = v;
    }
    __syncthreads();

    const float amp_raw = red[0] + red[1];

    if (tid < NH) {
        out_hd[(size_t)frame * NH + tid] = tk[tid] / amp_raw;
    }
    if (tid == 0) {
        out_amp[frame] = fminf(fmaxf(amp_raw * 2.0f, 0.0f), 1.0f);
    }
}

extern "C" void kernel_launch(void* const* d_in, const int* in_sizes, int n_in,
                              void* d_out, int out_size)
{
    const float* audio = (const float*)d_in[0];   // (2,250,1,1024) = 512000 f32
    const float* f0    = (const float*)d_in[1];   // (2,250,1)      = 500 f32

    const int frames = in_sizes[1];               // 500

    float* out_hd  = (float*)d_out;               // (frames, 64)
    float* out_amp = (float*)d_out + (size_t)frames * NH;  // (frames,)

    morlet_kernel<<<frames, THREADS>>>(audio, f0, out_hd, out_amp);
}

// round 8
// speedup vs baseline: 1.4090x; 1.4090x over previous
#include <cuda_runtime.h>

#define WIN       1024
#define NH        64
#define SEGS      8
#define SEGLEN    (WIN / SEGS)      // 128
#define THREADS   (NH * SEGS)       // 512

// amp-normalized Morlet harmonic transform via per-segment Goertzel.
// One block per (b,t,c) frame. Thread (k, seg) runs a real Goertzel recurrence
// over its 128-sample segment (2 fma-pipe ops/sample), then extracts the
// complex dot-product contribution with one exact sincospif phase correction.
__global__ __launch_bounds__(THREADS)
void morlet_kernel(const float* __restrict__ audio,
                   const float* __restrict__ f0,
                   float* __restrict__ out_hd,
                   float* __restrict__ out_amp)
{
    __shared__ float xw[WIN];
    __shared__ float pre[THREADS];
    __shared__ float pim[THREADS];
    __shared__ float tk[NH];
    __shared__ float red[2];

    const int frame = blockIdx.x;
    const int tid   = threadIdx.x;

    // normalizer = 1/sqrt(pi * 16000)
    const float normalizer = 0.00446031f;

    // Stage windowed samples: xw[n] = normalizer * exp(-(n-512)^2/16000) * x[n]
    const float* x = audio + (size_t)frame * WIN;
    #pragma unroll
    for (int n = tid; n < WIN; n += THREADS) {
        float d = (float)(n - WIN / 2);
        float g = __expf(-d * d * (1.0f / 16000.0f)) * normalizer;
        xw[n] = g * x[n];
    }
    __syncthreads();

    const int k   = tid & (NH - 1);      // harmonic index 0..63 (harmonic k+1)
    const int seg = tid >> 6;            // segment 0..7

    const float kf = (float)(k + 1);
    const float f  = f0[frame];
    const float fc = (f * kf) * (1.0f / 16000.0f);   // normalized frequency

    // omega = 2*pi*fc ; (sw, cw) = (sin w, cos w) exactly via sincospi
    float sw, cw;
    sincospif(2.0f * fc, &sw, &cw);
    const float c2 = 2.0f * cw;

    // Goertzel over this thread's 128-sample segment.
    float s1 = 0.0f, s2 = 0.0f;
    const float4* xv = (const float4*)(xw + seg * SEGLEN);
    #pragma unroll
    for (int i = 0; i < SEGLEN / 4; i++) {
        float4 w = xv[i];
        float s;
        s = fmaf(c2, s1, w.x - s2); s2 = s1; s1 = s;
        s = fmaf(c2, s1, w.y - s2); s2 = s1; s1 = s;
        s = fmaf(c2, s1, w.z - s2); s2 = s1; s1 = s;
        s = fmaf(c2, s1, w.w - s2); s2 = s1; s1 = s;
    }

    // y = s1 - e^{-jw}*s2  -> local result * e^{+jw(M-1)}
    float yre = fmaf(-cw, s2, s1);
    float yim = sw * s2;

    // Multiply by e^{-jw(n0 + M - 1)} to get  sum_{m} xw[n0+m] e^{-jw(n0+m)}
    const int n_end = seg * SEGLEN + SEGLEN - 1;
    float ph = fc * (float)n_end;
    float fr = ph - floorf(ph);
    float sp, cp;
    sincospif(-2.0f * fr, &sp, &cp);

    pre[tid] = cp * yre - sp * yim;
    pim[tid] = fmaf(cp, yim, sp * yre);
    __syncthreads();

    // Combine the 8 segment partials (complex sum BEFORE abs), take magnitude.
    if (tid < NH) {
        float re = 0.0f, im = 0.0f;
        #pragma unroll
        for (int s = 0; s < SEGS; s++) {
            re += pre[tid + s * NH];
            im += pim[tid + s * NH];
        }
        float t = sqrtf(fmaf(re, re, im * im));
        if (fc > 0.5f) t = 0.0f;   // Nyquist mask
        tk[tid] = t;
    }
    __syncthreads();

    // Sum over harmonics -> amp_raw
    if (tid < NH) {
        float v = tk[tid];
        #pragma unroll
        for (int o = 16; o > 0; o >>= 1)
            v += __shfl_down_sync(0xffffffffu, v, o);
        if ((tid & 31) == 0) red[tid >> 5] = v;
    }
    __syncthreads();

    const float amp_raw = red[0] + red[1];

    if (tid < NH) {
        out_hd[(size_t)frame * NH + tid] = tk[tid] / amp_raw;
    }
    if (tid == 0) {
        out_amp[frame] = fminf(fmaxf(amp_raw * 2.0f, 0.0f), 1.0f);
    }
}

extern "C" void kernel_launch(void* const* d_in, const int* in_sizes, int n_in,
                              void* d_out, int out_size)
{
    const float* audio = (const float*)d_in[0];   // (2,250,1,1024) = 512000 f32
    const float* f0    = (const float*)d_in[1];   // (2,250,1)      = 500 f32

    const int frames = in_sizes[1];               // 500

    float* out_hd  = (float*)d_out;               // (frames, 64)
    float* out_amp = (float*)d_out + (size_t)frames * NH;  // (frames,)

    morlet_kernel<<<frames, THREADS>>>(audio, f0, out_hd, out_amp);
}